// round 16
// baseline (speedup 1.0000x reference)
#include <cuda_runtime.h>
#include <cuda_fp16.h>
#include <cstdint>

#define N_TEMPL 4
#define N_RES   768
#define NROWS   (N_TEMPL * N_RES)
#define NCH     64
// fp16 gather table layout (102 columns):
//   cols 0..79  : (b,pb) pairs, col = 2*b+pb = (b<39 ? W[:,b] : 0) + pb*W[:,39]
//   cols 80..101: aa_j, col = 80+aa = W[:,40+aa]
#define NGCOLS  102
#define TBL_THREADS (NGCOLS * NCH)       // 6528

__device__ __half g_wt16[NGCOLS * NCH];    // 13 KB — L1-resident gather table
__device__ float  g_wt32[88 * NCH];        // fp32 transposed weights (dense consts)
__device__ float4 g_jrec[2 * NROWS];       // per-(t,res): [ca.xyz, pb.x], [pb.yz, flags, 0]
__device__ float4 g_frame[3 * NROWS];      // per-(t,res): M row-major (9) + pad

// Fused prelaunch: threads [0,6528) build tables, [6528,9600) build row records.
__global__ void prep_all(const float* __restrict__ lw,
                         const float* __restrict__ pos, const float* __restrict__ pb,
                         const float* __restrict__ pbm, const float* __restrict__ aam,
                         const int* __restrict__ aatype) {
    int gidx = blockIdx.x * blockDim.x + threadIdx.x;
    if (gidx < TBL_THREADS) {
        int c = gidx >> 6, o = gidx & 63;
        if (c < 80) {
            int b = c >> 1, pbbit = c & 1;
            float v = (b < 39) ? lw[o * 88 + b] : 0.0f;
            if (pbbit) v += lw[o * 88 + 39];
            g_wt16[gidx] = __float2half_rn(v);
        } else {
            g_wt16[gidx] = __float2half_rn(lw[o * 88 + 40 + (c - 80)]);
        }
        if (c < 88) g_wt32[c * NCH + o] = lw[o * 88 + c];
        return;
    }
    int idx = gidx - TBL_THREADS;
    if (idx >= NROWS) return;
    const float EPS = 1e-6f;

    const float* pr = pos + (size_t)idx * 37 * 3;
    float nx0 = pr[0], nx1 = pr[1], nx2 = pr[2];     // N
    float ca0 = pr[3], ca1 = pr[4], ca2 = pr[5];     // CA
    float cc0 = pr[6], cc1 = pr[7], cc2 = pr[8];     // C

    const float* pbr = pb + (size_t)idx * 3;
    float pb0 = pbr[0], pb1 = pbr[1], pb2v = pbr[2];

    const float* amr = aam + (size_t)idx * 37;
    float fm = amr[0] * amr[1] * amr[2];
    float pm = pbm[idx];
    int flags = aatype[idx];             // bits 0..4: aa
    if (pm != 0.0f) flags |= 1 << 5;     // pbm bit
    if (fm != 0.0f) flags |= 1 << 6;     // frame-mask bit

    g_jrec[2 * idx]     = make_float4(ca0, ca1, ca2, pb0);
    g_jrec[2 * idx + 1] = make_float4(pb1, pb2v, __int_as_float(flags), 0.0f);

    // rigid frame M = nr @ c2 @ c1  (rigid_vec = M @ (ca_j - ca_i))
    float n0 = nx0 - ca0, n1 = nx1 - ca1, n2 = nx2 - ca2;
    float c0 = cc0 - ca0, c1v = cc1 - ca1, c2v = cc2 - ca2;
    float d2xy = c0 * c0 + c1v * c1v;
    float norm1 = sqrtf(EPS + d2xy);
    float s1 = -c1v / norm1, co1 = c0 / norm1;
    float norm2 = sqrtf(EPS + d2xy + c2v * c2v);
    float s2 = c2v / norm2, co2 = sqrtf(d2xy) / norm2;
    float r00 = co2 * co1, r01 = -co2 * s1, r02 = s2;
    float r10 = s1,        r11 = co1,       r12 = 0.0f;
    float r20 = -s2 * co1, r21 = s2 * s1,   r22 = co2;
    float nyp = r10 * n0 + r11 * n1 + r12 * n2;
    float nzp = r20 * n0 + r21 * n1 + r22 * n2;
    float norm3 = sqrtf(EPS + nyp * nyp + nzp * nzp);
    float sn = -nzp / norm3, cn = nyp / norm3;

    g_frame[3 * idx]     = make_float4(r00, r01, r02, cn * r10 - sn * r20);
    g_frame[3 * idx + 1] = make_float4(cn * r11 - sn * r21, cn * r12 - sn * r22,
                                       sn * r10 + cn * r20, sn * r11 + cn * r21);
    g_frame[3 * idx + 2] = make_float4(sn * r12 + cn * r22, 0.0f, 0.0f, 0.0f);
}

// smem: sData 768*16 = 12288 B + sRow ≈ 12.4 KB (6 CTAs = 75 KB)
__global__ __launch_bounds__(256, 6) void tpe_kernel(
    const float* __restrict__ lb,       // [64]
    float* __restrict__ out)            // [T,768,768,64]
{
    __shared__ float4 sData[N_RES];   // uvx, uvy, uvz, packed(bpCol | aaCol<<7 | fm<<14)
    __shared__ float4 sRow[5];        // frame (3) + jrec_i (2)

    const float EPS = 1e-6f;
    const int row = blockIdx.x;       // t*768 + i
    const int tid = threadIdx.x;

    // ---- Phase 0: row constants ----------------------------------------------
    if (tid < 3) sRow[tid] = g_frame[3 * row + tid];
    else if (tid < 5) sRow[tid] = g_jrec[2 * row + (tid - 3)];
    __syncthreads();

    const float4 i1 = sRow[4];
    const int iflags = __float_as_int(i1.z);

    // ---------------- Phase 1: per-j scalars (2 coalesced float4 per j) -------
    {
        const float4 f0 = sRow[0], f1 = sRow[1], f2 = sRow[2];
        const float4 i0 = sRow[3];
        const float m0 = f0.x, m1 = f0.y, m2 = f0.z;
        const float m3 = f0.w, m4 = f1.x, m5 = f1.y;
        const float m6 = f1.z, m7 = f1.w, m8 = f2.x;
        const float cai0 = i0.x, cai1 = i0.y, cai2 = i0.z;
        const float pbi0 = i0.w, pbi1 = i1.x, pbi2 = i1.y;
        const int tbase = (row / N_RES) * N_RES;

        for (int j = tid; j < N_RES; j += 256) {
            float4 j0r = g_jrec[2 * (tbase + j)];
            float4 j1r = g_jrec[2 * (tbase + j) + 1];
            int jflags = __float_as_int(j1r.z);

            // distogram bin (match reference FP ordering)
            float dx = __fadd_rn(pbi0, -j0r.w);
            float dy = __fadd_rn(pbi1, -j1r.x);
            float dz = __fadd_rn(pbi2, -j1r.y);
            float dsq = __fadd_rn(__fadd_rn(__fmul_rn(dx, dx), __fmul_rn(dy, dy)),
                                  __fmul_rn(dz, dz));
            int k = (int)floorf((sqrtf(dsq) - 3.25f) * 0.8f);
            k = min(max(k, -1), 38);
            int bin = -1;
            int clo = max(k - 1, 0), chi = min(k + 1, 38);
            #pragma unroll
            for (int c = 0; c < 3; ++c) {
                int cand = clo + c;
                if (cand > chi) break;
                float lbv = 3.25f + (float)cand * 1.25f;  lbv = lbv * lbv;
                float ubv = (cand == 38) ? 1e8f
                           : (3.25f + (float)(cand + 1) * 1.25f) *
                             (3.25f + (float)(cand + 1) * 1.25f);
                if (dsq > lbv && dsq < ubv) { bin = cand; break; }
            }

            // rigid vec + unit vector
            float ddx = j0r.x - cai0, ddy = j0r.y - cai1, ddz = j0r.z - cai2;
            float rvx = m0 * ddx + m1 * ddy + m2 * ddz;
            float rvy = m3 * ddx + m4 * ddy + m5 * ddz;
            float rvz = m6 * ddx + m7 * ddy + m8 * ddz;
            float inv = 1.0f / sqrtf(EPS + (rvx * rvx + rvy * rvy + rvz * rvz));

            int binCol = (bin < 0) ? 39 : bin;
            int pbbit = ((iflags & jflags) >> 5) & 1;
            int bp = binCol * 2 + pbbit;
            int aaCol = 80 + (jflags & 31);
            int packed = bp | (aaCol << 7) | (((iflags & jflags) & (1 << 6)) << 8); // fm at bit 14
            sData[j] = make_float4(rvx * inv, rvy * inv, rvz * inv,
                                   __int_as_float(packed));
        }
    }
    __syncthreads();

    // ---------------- Phase 2: 16 ch-threads, single j per iter ---------------
    const int oq = tid & 15;
    const int jl = tid >> 4;          // 0..15
    const int ob = oq * 4;

    float4 rowb, w84v, w85v, w86v, bv;
    {
        int ai = iflags & 31;
        float4 wai = *(const float4*)&g_wt32[(62 + ai) * NCH + ob];
        float4 w87 = *(const float4*)&g_wt32[87 * NCH + ob];
        rowb = make_float4(wai.x + w87.x, wai.y + w87.y, wai.z + w87.z, wai.w + w87.w);
        w84v = *(const float4*)&g_wt32[84 * NCH + ob];
        w85v = *(const float4*)&g_wt32[85 * NCH + ob];
        w86v = *(const float4*)&g_wt32[86 * NCH + ob];
        bv   = *(const float4*)&lb[ob];
    }

    float* orow = out + (size_t)row * N_RES * NCH;

    #pragma unroll 2
    for (int jb = 0; jb < N_RES; jb += 16) {
        int j = jb + jl;

        float4 d = sData[j];
        int p = __float_as_int(d.w);
        // Direct L1-resident gathers from the 13 KB global table (no smem copy).
        uint2 gbv = __ldg((const uint2*)&g_wt16[((p & 127) << 6) + ob]);
        uint2 gav = __ldg((const uint2*)&g_wt16[(((p >> 7) & 127) << 6) + ob]);
        __half2 h0 = *(__half2*)&gbv.x, h1 = *(__half2*)&gbv.y;
        __half2 h2 = *(__half2*)&gav.x, h3 = *(__half2*)&gav.y;

        float2 c01 = __half22float2(__hadd2(h0, h2));
        float2 c23 = __half22float2(__hadd2(h1, h3));
        float fm = (p & (1 << 14)) ? 1.0f : 0.0f;

        float4 r;
        {
            float s;
            s = rowb.x + c01.x;
            s = fmaf(d.x, w84v.x, s); s = fmaf(d.y, w85v.x, s); s = fmaf(d.z, w86v.x, s);
            r.x = fmaf(fm, s, bv.x);
            s = rowb.y + c01.y;
            s = fmaf(d.x, w84v.y, s); s = fmaf(d.y, w85v.y, s); s = fmaf(d.z, w86v.y, s);
            r.y = fmaf(fm, s, bv.y);
            s = rowb.z + c23.x;
            s = fmaf(d.x, w84v.z, s); s = fmaf(d.y, w85v.z, s); s = fmaf(d.z, w86v.z, s);
            r.z = fmaf(fm, s, bv.z);
            s = rowb.w + c23.y;
            s = fmaf(d.x, w84v.w, s); s = fmaf(d.y, w85v.w, s); s = fmaf(d.z, w86v.w, s);
            r.w = fmaf(fm, s, bv.w);
        }
        // A/B experiment: plain store (write-back, L2-allocating) instead of __stcs
        *(float4*)&orow[(size_t)j * NCH + ob] = r;
    }
}

extern "C" void kernel_launch(void* const* d_in, const int* in_sizes, int n_in,
                              void* d_out, int out_size) {
    const float* pos    = (const float*)d_in[0];  // [4,768,37,3]
    const float* pb     = (const float*)d_in[1];  // [4,768,3]
    const float* pbmask = (const float*)d_in[2];  // [4,768]
    const float* aamask = (const float*)d_in[3];  // [4,768,37]
    const int*   aatype = (const int*)  d_in[4];  // [4,768]
    const float* lw     = (const float*)d_in[5];  // [64,88]
    const float* lb     = (const float*)d_in[6];  // [64]
    float* out = (float*)d_out;

    prep_all<<<(TBL_THREADS + NROWS + 255) / 256, 256>>>(lw, pos, pb, pbmask, aamask, aatype);
    tpe_kernel<<<NROWS, 256>>>(lb, out);
}

// round 17
// speedup vs baseline: 1.0349x; 1.0349x over previous
#include <cuda_runtime.h>
#include <cuda_fp16.h>
#include <cstdint>

#define N_TEMPL 4
#define N_RES   768
#define NROWS   (N_TEMPL * N_RES)
#define NCH     64
// fp16 gather table layout (102 columns):
//   cols 0..79  : (b,pb) pairs, col = 2*b+pb = (b<39 ? W[:,b] : 0) + pb*W[:,39]
//   cols 80..101: aa_j, col = 80+aa = W[:,40+aa]
#define NGCOLS  102
#define TBL_THREADS (NGCOLS * NCH)       // 6528

__device__ __half g_wt16[NGCOLS * NCH];
__device__ float  g_wt32[88 * NCH];        // fp32 transposed weights (dense consts)
__device__ float4 g_jrec[2 * NROWS];       // per-(t,res): [ca.xyz, pb.x], [pb.yz, flags, 0]
__device__ float4 g_frame[3 * NROWS];      // per-(t,res): M row-major (9) + pad

// Fused prelaunch: threads [0,6528) build tables, [6528,9600) build row records.
__global__ void prep_all(const float* __restrict__ lw,
                         const float* __restrict__ pos, const float* __restrict__ pb,
                         const float* __restrict__ pbm, const float* __restrict__ aam,
                         const int* __restrict__ aatype) {
    int gidx = blockIdx.x * blockDim.x + threadIdx.x;
    if (gidx < TBL_THREADS) {
        int c = gidx >> 6, o = gidx & 63;
        if (c < 80) {
            int b = c >> 1, pbbit = c & 1;
            float v = (b < 39) ? lw[o * 88 + b] : 0.0f;
            if (pbbit) v += lw[o * 88 + 39];
            g_wt16[gidx] = __float2half_rn(v);
        } else {
            g_wt16[gidx] = __float2half_rn(lw[o * 88 + 40 + (c - 80)]);
        }
        if (c < 88) g_wt32[c * NCH + o] = lw[o * 88 + c];
        return;
    }
    int idx = gidx - TBL_THREADS;
    if (idx >= NROWS) return;
    const float EPS = 1e-6f;

    const float* pr = pos + (size_t)idx * 37 * 3;
    float nx0 = pr[0], nx1 = pr[1], nx2 = pr[2];     // N
    float ca0 = pr[3], ca1 = pr[4], ca2 = pr[5];     // CA
    float cc0 = pr[6], cc1 = pr[7], cc2 = pr[8];     // C

    const float* pbr = pb + (size_t)idx * 3;
    float pb0 = pbr[0], pb1 = pbr[1], pb2v = pbr[2];

    const float* amr = aam + (size_t)idx * 37;
    float fm = amr[0] * amr[1] * amr[2];
    float pm = pbm[idx];
    int flags = aatype[idx];             // bits 0..4: aa
    if (pm != 0.0f) flags |= 1 << 5;     // pbm bit
    if (fm != 0.0f) flags |= 1 << 6;     // frame-mask bit

    g_jrec[2 * idx]     = make_float4(ca0, ca1, ca2, pb0);
    g_jrec[2 * idx + 1] = make_float4(pb1, pb2v, __int_as_float(flags), 0.0f);

    // rigid frame M = nr @ c2 @ c1  (rigid_vec = M @ (ca_j - ca_i))
    float n0 = nx0 - ca0, n1 = nx1 - ca1, n2 = nx2 - ca2;
    float c0 = cc0 - ca0, c1v = cc1 - ca1, c2v = cc2 - ca2;
    float d2xy = c0 * c0 + c1v * c1v;
    float norm1 = sqrtf(EPS + d2xy);
    float s1 = -c1v / norm1, co1 = c0 / norm1;
    float norm2 = sqrtf(EPS + d2xy + c2v * c2v);
    float s2 = c2v / norm2, co2 = sqrtf(d2xy) / norm2;
    float r00 = co2 * co1, r01 = -co2 * s1, r02 = s2;
    float r10 = s1,        r11 = co1,       r12 = 0.0f;
    float r20 = -s2 * co1, r21 = s2 * s1,   r22 = co2;
    float nyp = r10 * n0 + r11 * n1 + r12 * n2;
    float nzp = r20 * n0 + r21 * n1 + r22 * n2;
    float norm3 = sqrtf(EPS + nyp * nyp + nzp * nzp);
    float sn = -nzp / norm3, cn = nyp / norm3;

    g_frame[3 * idx]     = make_float4(r00, r01, r02, cn * r10 - sn * r20);
    g_frame[3 * idx + 1] = make_float4(cn * r11 - sn * r21, cn * r12 - sn * r22,
                                       sn * r10 + cn * r20, sn * r11 + cn * r21);
    g_frame[3 * idx + 2] = make_float4(sn * r12 + cn * r22, 0.0f, 0.0f, 0.0f);
}

// smem: Wt_h 13056 B + sData 768*16 = 12288 B + sRow ≈ 25.4 KB (6 CTAs = 153 KB)
__global__ __launch_bounds__(256, 6) void tpe_kernel(
    const float* __restrict__ lb,       // [64]
    float* __restrict__ out)            // [T,768,768,64]
{
    __shared__ alignas(16) __half Wt_h[NGCOLS * NCH];
    __shared__ float4 sData[N_RES];   // uvx, uvy, uvz, packed(bpCol | aaCol<<7 | fm<<14)
    __shared__ float4 sRow[5];        // frame (3) + jrec_i (2)

    const float EPS = 1e-6f;
    const int row = blockIdx.x;       // t*768 + i
    const int tid = threadIdx.x;

    // ---- Phase 0: coalesced table copy + row constants -----------------------
    {
        const uint4* src = (const uint4*)g_wt16;     // 13056 B = 816 uint4
        uint4* dst = (uint4*)Wt_h;
        #pragma unroll
        for (int idx = tid; idx < 816; idx += 256) dst[idx] = src[idx];
    }
    if (tid < 3) sRow[tid] = g_frame[3 * row + tid];
    else if (tid < 5) sRow[tid] = g_jrec[2 * row + (tid - 3)];
    __syncthreads();

    const float4 i1 = sRow[4];
    const int iflags = __float_as_int(i1.z);

    // ---------------- Phase 1: per-j scalars (2 coalesced float4 per j) -------
    {
        const float4 f0 = sRow[0], f1 = sRow[1], f2 = sRow[2];
        const float4 i0 = sRow[3];
        const float m0 = f0.x, m1 = f0.y, m2 = f0.z;
        const float m3 = f0.w, m4 = f1.x, m5 = f1.y;
        const float m6 = f1.z, m7 = f1.w, m8 = f2.x;
        const float cai0 = i0.x, cai1 = i0.y, cai2 = i0.z;
        const float pbi0 = i0.w, pbi1 = i1.x, pbi2 = i1.y;
        const int tbase = (row / N_RES) * N_RES;

        for (int j = tid; j < N_RES; j += 256) {
            float4 j0r = g_jrec[2 * (tbase + j)];
            float4 j1r = g_jrec[2 * (tbase + j) + 1];
            int jflags = __float_as_int(j1r.z);

            // distogram bin (match reference FP ordering)
            float dx = __fadd_rn(pbi0, -j0r.w);
            float dy = __fadd_rn(pbi1, -j1r.x);
            float dz = __fadd_rn(pbi2, -j1r.y);
            float dsq = __fadd_rn(__fadd_rn(__fmul_rn(dx, dx), __fmul_rn(dy, dy)),
                                  __fmul_rn(dz, dz));
            int k = (int)floorf((sqrtf(dsq) - 3.25f) * 0.8f);
            k = min(max(k, -1), 38);
            int bin = -1;
            int clo = max(k - 1, 0), chi = min(k + 1, 38);
            #pragma unroll
            for (int c = 0; c < 3; ++c) {
                int cand = clo + c;
                if (cand > chi) break;
                float lbv = 3.25f + (float)cand * 1.25f;  lbv = lbv * lbv;
                float ubv = (cand == 38) ? 1e8f
                           : (3.25f + (float)(cand + 1) * 1.25f) *
                             (3.25f + (float)(cand + 1) * 1.25f);
                if (dsq > lbv && dsq < ubv) { bin = cand; break; }
            }

            // rigid vec + unit vector
            float ddx = j0r.x - cai0, ddy = j0r.y - cai1, ddz = j0r.z - cai2;
            float rvx = m0 * ddx + m1 * ddy + m2 * ddz;
            float rvy = m3 * ddx + m4 * ddy + m5 * ddz;
            float rvz = m6 * ddx + m7 * ddy + m8 * ddz;
            float inv = 1.0f / sqrtf(EPS + (rvx * rvx + rvy * rvy + rvz * rvz));

            int binCol = (bin < 0) ? 39 : bin;
            int pbbit = ((iflags & jflags) >> 5) & 1;
            int bp = binCol * 2 + pbbit;
            int aaCol = 80 + (jflags & 31);
            int packed = bp | (aaCol << 7) | (((iflags & jflags) & (1 << 6)) << 8); // fm at bit 14
            sData[j] = make_float4(rvx * inv, rvy * inv, rvz * inv,
                                   __int_as_float(packed));
        }
    }
    __syncthreads();

    // ---------------- Phase 2: 16 ch-threads, single j per iter ---------------
    const int oq = tid & 15;
    const int jl = tid >> 4;          // 0..15
    const int ob = oq * 4;

    float4 rowb, w84v, w85v, w86v, bv;
    {
        int ai = iflags & 31;
        float4 wai = *(const float4*)&g_wt32[(62 + ai) * NCH + ob];
        float4 w87 = *(const float4*)&g_wt32[87 * NCH + ob];
        rowb = make_float4(wai.x + w87.x, wai.y + w87.y, wai.z + w87.z, wai.w + w87.w);
        w84v = *(const float4*)&g_wt32[84 * NCH + ob];
        w85v = *(const float4*)&g_wt32[85 * NCH + ob];
        w86v = *(const float4*)&g_wt32[86 * NCH + ob];
        bv   = *(const float4*)&lb[ob];
    }

    float* orow = out + (size_t)row * N_RES * NCH;

    #pragma unroll 2
    for (int jb = 0; jb < N_RES; jb += 16) {
        int j = jb + jl;

        float4 d = sData[j];
        int p = __float_as_int(d.w);
        const __half2* gb = (const __half2*)&Wt_h[((p & 127) << 6) + ob];
        const __half2* ga = (const __half2*)&Wt_h[(((p >> 7) & 127) << 6) + ob];
        __half2 h0 = gb[0], h1 = gb[1], h2 = ga[0], h3 = ga[1];

        float2 c01 = __half22float2(__hadd2(h0, h2));
        float2 c23 = __half22float2(__hadd2(h1, h3));
        float fm = (p & (1 << 14)) ? 1.0f : 0.0f;

        float4 r;
        {
            float s;
            s = rowb.x + c01.x;
            s = fmaf(d.x, w84v.x, s); s = fmaf(d.y, w85v.x, s); s = fmaf(d.z, w86v.x, s);
            r.x = fmaf(fm, s, bv.x);
            s = rowb.y + c01.y;
            s = fmaf(d.x, w84v.y, s); s = fmaf(d.y, w85v.y, s); s = fmaf(d.z, w86v.y, s);
            r.y = fmaf(fm, s, bv.y);
            s = rowb.z + c23.x;
            s = fmaf(d.x, w84v.z, s); s = fmaf(d.y, w85v.z, s); s = fmaf(d.z, w86v.z, s);
            r.z = fmaf(fm, s, bv.z);
            s = rowb.w + c23.y;
            s = fmaf(d.x, w84v.w, s); s = fmaf(d.y, w85v.w, s); s = fmaf(d.z, w86v.w, s);
            r.w = fmaf(fm, s, bv.w);
        }
        __stcs((float4*)&orow[(size_t)j * NCH + ob], r);
    }
}

extern "C" void kernel_launch(void* const* d_in, const int* in_sizes, int n_in,
                              void* d_out, int out_size) {
    const float* pos    = (const float*)d_in[0];  // [4,768,37,3]
    const float* pb     = (const float*)d_in[1];  // [4,768,3]
    const float* pbmask = (const float*)d_in[2];  // [4,768]
    const float* aamask = (const float*)d_in[3];  // [4,768,37]
    const int*   aatype = (const int*)  d_in[4];  // [4,768]
    const float* lw     = (const float*)d_in[5];  // [64,88]
    const float* lb     = (const float*)d_in[6];  // [64]
    float* out = (float*)d_out;

    prep_all<<<(TBL_THREADS + NROWS + 255) / 256, 256>>>(lw, pos, pb, pbmask, aamask, aatype);
    tpe_kernel<<<NROWS, 256>>>(lb, out);
}